// round 13
// baseline (speedup 1.0000x reference)
#include <cuda_runtime.h>
#include <cuda_fp16.h>
#include <cstdint>
#include <math.h>

#define LQ 8192
#define LK 8192
#define DIM 128
#define KCH 8
#define SCALE 0.08838834764831845f  // 1/sqrt(128)

#define STRQ 136  // fp16 elems per smem row, 128-wide tiles (272B, conflict-free)
#define STRP 72   // fp16 elems per smem row, 64-wide tiles (144B)

// ---------------- device scratch ----------------
__device__ __half g_qh[(size_t)LQ * DIM];
__device__ __half g_kh[(size_t)LK * DIM];
__device__ __half g_vth[(size_t)DIM * LK];          // V^T [d][k]
__device__ float g_lpart[(size_t)LQ * 64];
__device__ float g_il[LQ];
__device__ float g_opart[(size_t)KCH * LQ * DIM];

// ---------------- helpers ----------------
__device__ __forceinline__ uint32_t smem_u32(const void* p) {
    uint32_t a;
    asm("{ .reg .u64 t; cvta.to.shared.u64 t, %1; cvt.u32.u64 %0, t; }" : "=r"(a) : "l"(p));
    return a;
}
__device__ __forceinline__ void ldsm4(uint32_t (&r)[4], uint32_t addr) {
    asm volatile("ldmatrix.sync.aligned.m8n8.x4.shared.b16 {%0,%1,%2,%3}, [%4];"
        : "=r"(r[0]), "=r"(r[1]), "=r"(r[2]), "=r"(r[3]) : "r"(addr));
}
__device__ __forceinline__ void mma16816(float (&c)[4], const uint32_t (&a)[4],
                                         uint32_t b0, uint32_t b1) {
    asm volatile("mma.sync.aligned.m16n8k16.row.col.f32.f16.f16.f32 "
        "{%0,%1,%2,%3}, {%4,%5,%6,%7}, {%8,%9}, {%0,%1,%2,%3};"
        : "+f"(c[0]), "+f"(c[1]), "+f"(c[2]), "+f"(c[3])
        : "r"(a[0]), "r"(a[1]), "r"(a[2]), "r"(a[3]), "r"(b0), "r"(b1));
}
__device__ __forceinline__ void cpasync16(uint32_t dst, const void* src) {
    asm volatile("cp.async.cg.shared.global [%0], [%1], 16;" :: "r"(dst), "l"(src));
}
#define CP_COMMIT() asm volatile("cp.async.commit_group;" ::: "memory")
#define CP_WAIT(N)  asm volatile("cp.async.wait_group %0;" :: "n"(N) : "memory")
__device__ __forceinline__ uint32_t h2u(__half2 h) { return *reinterpret_cast<uint32_t*>(&h); }

// ---------------------------------------------------------------------------
// prep: fp32 -> fp16 (Q prescaled, K, V transposed)
// ---------------------------------------------------------------------------
__global__ __launch_bounds__(256) void prep_kernel(const float* __restrict__ Q,
                                                   const float* __restrict__ K,
                                                   const float* __restrict__ V) {
    size_t i = (size_t)blockIdx.x * 256 + threadIdx.x;
    g_qh[i] = __float2half_rn(Q[i] * SCALE);
    g_kh[i] = __float2half_rn(K[i]);
    size_t kr = i >> 7, d = i & 127;
    g_vth[d * LK + kr] = __float2half_rn(V[i]);
}

// ---------------------------------------------------------------------------
// Kernel A1: row partial sums of exp(Qs @ K^T). 128m x 128n per CTA, no store.
// Warp tile 32m x 64n. Same k16 accumulation order as fused QK.
// ---------------------------------------------------------------------------
__global__ __launch_bounds__(256, 2) void qk_sums_kernel() {
    extern __shared__ __align__(16) char smem[];
    __half* Qh = (__half*)smem;            // [128][STRQ]
    __half* Kh = Qh + 128 * STRQ;          // [128][STRQ]

    const int tid = threadIdx.x, lane = tid & 31, wid = tid >> 5;
    const int m0 = blockIdx.y * 128, n0 = blockIdx.x * 128;

    const uint32_t qhb = smem_u32(Qh), khb = smem_u32(Kh);

#pragma unroll
    for (int i = 0; i < 8; i++) {
        int idx = i * 256 + tid;
        int row = idx >> 4, seg = idx & 15;
        cpasync16(qhb + row * 272 + seg * 16, g_qh + (size_t)(m0 + row) * DIM + seg * 8);
    }
#pragma unroll
    for (int i = 0; i < 8; i++) {
        int idx = i * 256 + tid;
        int row = idx >> 4, seg = idx & 15;
        cpasync16(khb + row * 272 + seg * 16, g_kh + (size_t)(n0 + row) * DIM + seg * 8);
    }
    CP_COMMIT();
    CP_WAIT(0);
    __syncthreads();

    const int wm = (wid >> 1) * 32, wn = (wid & 1) * 64;
    float c[2][8][4];
#pragma unroll
    for (int mi = 0; mi < 2; mi++)
#pragma unroll
        for (int nj = 0; nj < 8; nj++)
#pragma unroll
            for (int e = 0; e < 4; e++) c[mi][nj][e] = 0.f;

    const int arow = lane & 15;
    const int acol = (lane >> 4) * 8;

#pragma unroll
    for (int k16 = 0; k16 < 8; k16++) {
        const int kc = k16 * 16 + acol;
        uint32_t a[2][4], b[4][4];
#pragma unroll
        for (int mi = 0; mi < 2; mi++)
            ldsm4(a[mi], qhb + ((wm + mi * 16 + arow) * STRQ + kc) * 2);
#pragma unroll
        for (int nj = 0; nj < 4; nj++)
            ldsm4(b[nj], khb + ((wn + nj * 16 + arow) * STRQ + kc) * 2);
#pragma unroll
        for (int mi = 0; mi < 2; mi++)
#pragma unroll
            for (int nj = 0; nj < 4; nj++) {
                mma16816(c[mi][2 * nj], a[mi], b[nj][0], b[nj][2]);
                mma16816(c[mi][2 * nj + 1], a[mi], b[nj][1], b[nj][3]);
            }
    }

#pragma unroll
    for (int mi = 0; mi < 2; mi++)
#pragma unroll
        for (int nj = 0; nj < 8; nj++)
#pragma unroll
            for (int e = 0; e < 4; e++) c[mi][nj][e] = __expf(c[mi][nj][e]);

    __syncthreads();
    float* rs = (float*)smem;  // [128][2]
#pragma unroll
    for (int mi = 0; mi < 2; mi++) {
        float v0 = 0.f, v1 = 0.f;
#pragma unroll
        for (int nj = 0; nj < 8; nj++) {
            v0 += c[mi][nj][0] + c[mi][nj][1];
            v1 += c[mi][nj][2] + c[mi][nj][3];
        }
        v0 += __shfl_xor_sync(0xffffffffu, v0, 1);
        v0 += __shfl_xor_sync(0xffffffffu, v0, 2);
        v1 += __shfl_xor_sync(0xffffffffu, v1, 1);
        v1 += __shfl_xor_sync(0xffffffffu, v1, 2);
        if ((lane & 3) == 0) {
            int r = wm + mi * 16 + (lane >> 2);
            rs[r * 2 + (wid & 1)] = v0;
            rs[(r + 8) * 2 + (wid & 1)] = v1;
        }
    }
    __syncthreads();
    if (tid < 128) {
        g_lpart[(size_t)(m0 + tid) * 64 + blockIdx.x] = rs[tid * 2] + rs[tid * 2 + 1];
    }
}

// ---------------------------------------------------------------------------
// Kernel B: l = sum of partials (fixed order), store 1/l.
// ---------------------------------------------------------------------------
__global__ __launch_bounds__(256) void lred_kernel() {
    const int row = blockIdx.x * 256 + threadIdx.x;
    const float4* p = (const float4*)(g_lpart + (size_t)row * 64);
    float s = 0.f;
#pragma unroll
    for (int i = 0; i < 16; i++) {
        float4 v = p[i];
        s += v.x + v.y + v.z + v.w;
    }
    g_il[row] = 1.0f / s;
}

// ---------------------------------------------------------------------------
// Kernel A2 (fused, register-chained): per 64q CTA and 64k iter:
//   c = Q@K^T (warp 16q x 32n, Q-frags for k16 0..3 hoisted in regs)
//   -> p = exp(c)*il -> att store -> p repacked as PV A-frags -> o += p @ V.
// Epilogue: n-half partials merged in smem -> KCH opart chunks.
// ---------------------------------------------------------------------------
__global__ __launch_bounds__(256, 2) void fused_kernel(float* __restrict__ att) {
    extern __shared__ __align__(16) char smem[];
    const uint32_t qb = smem_u32(smem);
    const uint32_t kbb = qb + 17408;        // K: 2 x [64][STRQ]
    const uint32_t vbb = kbb + 2 * 17408;   // V: 2 x [128][STRP]
    const int KBUF = 17408, VBUF = 18432;

    const int tid = threadIdx.x, lane = tid & 31, wid = tid >> 5;
    const int q0 = blockIdx.y * 64;
    const int kbase = blockIdx.x * (LK / KCH);

    const int arow = lane & 15, acol = (lane >> 4) * 8;
    const int r0 = lane >> 2, c0 = (lane & 3) * 2;
    const int wq = (wid >> 1) * 16;         // warp's 16 q-rows
    const int wn = (wid & 1) * 32;          // warp's 32-k (= QK n) slice

    const float il0 = g_il[q0 + wq + r0];
    const float il1 = g_il[q0 + wq + r0 + 8];

    // prologue: Q as group 0; K(0)+V(0) as group 1
#pragma unroll
    for (int i = 0; i < 4; i++) {
        int idx = i * 256 + tid;
        int row = idx >> 4, seg = idx & 15;
        cpasync16(qb + row * 272 + seg * 16, g_qh + (size_t)(q0 + row) * DIM + seg * 8);
    }
    CP_COMMIT();
#pragma unroll
    for (int i = 0; i < 4; i++) {
        int idx = i * 256 + tid;
        int row = idx >> 4, seg = idx & 15;
        cpasync16(kbb + row * 272 + seg * 16, g_kh + (size_t)(kbase + row) * DIM + seg * 8);
    }
#pragma unroll
    for (int i = 0; i < 4; i++) {
        int idx = i * 256 + tid;
        int row = idx >> 3, seg = idx & 7;
        cpasync16(vbb + row * 144 + seg * 16, g_vth + (size_t)row * LK + kbase + seg * 8);
    }
    CP_COMMIT();

    // Q resident -> hoist A-frags for k16 0..3
    CP_WAIT(1);
    __syncthreads();
    uint32_t aq[4][4];
#pragma unroll
    for (int k16 = 0; k16 < 4; k16++)
        ldsm4(aq[k16], qb + ((wq + arow) * STRQ + k16 * 16 + acol) * 2);

    float o[16][4];
#pragma unroll
    for (int nj = 0; nj < 16; nj++)
#pragma unroll
        for (int e = 0; e < 4; e++) o[nj][e] = 0.f;

    for (int t = 0; t < 16; t++) {
        CP_WAIT(0);           // K(t), V(t) resident
        __syncthreads();      // all warps done with buffers from iter t-1

        if (t < 15) {
            const int ktn = kbase + (t + 1) * 64;
            const uint32_t kdst = kbb + ((t + 1) & 1) * KBUF;
            const uint32_t vdst = vbb + ((t + 1) & 1) * VBUF;
#pragma unroll
            for (int i = 0; i < 4; i++) {
                int idx = i * 256 + tid;
                int row = idx >> 4, seg = idx & 15;
                cpasync16(kdst + row * 272 + seg * 16,
                          g_kh + (size_t)(ktn + row) * DIM + seg * 8);
            }
#pragma unroll
            for (int i = 0; i < 4; i++) {
                int idx = i * 256 + tid;
                int row = idx >> 3, seg = idx & 7;
                cpasync16(vdst + row * 144 + seg * 16,
                          g_vth + (size_t)row * LK + ktn + seg * 8);
            }
        }
        CP_COMMIT();

        const uint32_t kcur = kbb + (t & 1) * KBUF;
        const uint32_t vcur = vbb + (t & 1) * VBUF;
        const int kt0 = kbase + t * 64;

        // --- QK: warp tile 16q x 32n; Q A-frags hoisted for k16<4 ---
        float c[4][4];
#pragma unroll
        for (int n8 = 0; n8 < 4; n8++)
#pragma unroll
            for (int e = 0; e < 4; e++) c[n8][e] = 0.f;

#pragma unroll
        for (int k16 = 0; k16 < 8; k16++) {
            const int kc = k16 * 16 + acol;
            uint32_t at[4], b0[4], b1[4];
            const uint32_t* ap;
            if (k16 < 4) {
                ap = aq[k16];
            } else {
                ldsm4(at, qb + ((wq + arow) * STRQ + kc) * 2);
                ap = at;
            }
            ldsm4(b0, kcur + ((wn + arow) * STRQ + kc) * 2);
            ldsm4(b1, kcur + ((wn + 16 + arow) * STRQ + kc) * 2);
            mma16816(c[0], *(const uint32_t(*)[4])ap, b0[0], b0[2]);
            mma16816(c[1], *(const uint32_t(*)[4])ap, b0[1], b0[3]);
            mma16816(c[2], *(const uint32_t(*)[4])ap, b1[0], b1[2]);
            mma16816(c[3], *(const uint32_t(*)[4])ap, b1[1], b1[3]);
        }

        // --- p = exp(c)*il, att store ---
#pragma unroll
        for (int n8 = 0; n8 < 4; n8++) {
            c[n8][0] = __expf(c[n8][0]) * il0;
            c[n8][1] = __expf(c[n8][1]) * il0;
            c[n8][2] = __expf(c[n8][2]) * il1;
            c[n8][3] = __expf(c[n8][3]) * il1;
        }
#pragma unroll
        for (int n8 = 0; n8 < 4; n8++) {
            size_t row = (size_t)(q0 + wq + r0);
            size_t col = (size_t)(kt0 + wn + n8 * 8 + c0);
            *(float2*)(att + row * LK + col) = make_float2(c[n8][0], c[n8][1]);
            *(float2*)(att + (row + 8) * LK + col) = make_float2(c[n8][2], c[n8][3]);
        }

        // --- PV: C frags repacked as A frags; warp's k-slice = wn..wn+32 ---
#pragma unroll
        for (int kk = 0; kk < 2; kk++) {
            uint32_t ah[4];
            ah[0] = h2u(__floats2half2_rn(c[2 * kk][0], c[2 * kk][1]));
            ah[1] = h2u(__floats2half2_rn(c[2 * kk][2], c[2 * kk][3]));
            ah[2] = h2u(__floats2half2_rn(c[2 * kk + 1][0], c[2 * kk + 1][1]));
            ah[3] = h2u(__floats2half2_rn(c[2 * kk + 1][2], c[2 * kk + 1][3]));
#pragma unroll
            for (int g = 0; g < 8; g++) {
                uint32_t bv[4];
                ldsm4(bv, vcur + ((g * 16 + arow) * STRP + wn + kk * 16 + acol) * 2);
                mma16816(o[2 * g], ah, bv[0], bv[2]);
                mma16816(o[2 * g + 1], ah, bv[1], bv[3]);
            }
        }
    }

    // --- epilogue: merge n-half partials in smem -> one chunk per k-chunk ---
    __syncthreads();   // everyone done reading Q/K/V smem
    float* xb = (float*)smem;   // [4 qg][32 lanes][65] floats = 33280 B
    if (wid & 1) {
        float* dst = xb + (wid >> 1) * (32 * 65) + lane * 65;
#pragma unroll
        for (int n8 = 0; n8 < 16; n8++) {
#pragma unroll
            for (int e = 0; e < 4; e++) dst[n8 * 4 + e] = o[n8][e];
        }
    }
    __syncthreads();
    if (!(wid & 1)) {
        const float* src = xb + (wid >> 1) * (32 * 65) + lane * 65;
        float* op = g_opart + (size_t)blockIdx.x * ((size_t)LQ * DIM);
#pragma unroll
        for (int n8 = 0; n8 < 16; n8++) {
            float2 lo = make_float2(o[n8][0] + src[n8 * 4 + 0], o[n8][1] + src[n8 * 4 + 1]);
            float2 hi = make_float2(o[n8][2] + src[n8 * 4 + 2], o[n8][3] + src[n8 * 4 + 3]);
            size_t row = (size_t)(q0 + wq + r0);
            size_t col = (size_t)(n8 * 8 + c0);
            *(float2*)(op + row * DIM + col) = lo;
            *(float2*)(op + (row + 8) * DIM + col) = hi;
        }
    }
}

// ---------------------------------------------------------------------------
// Kernel D: reduce KCH partials into out (P pre-normalized -> plain sum).
// ---------------------------------------------------------------------------
__global__ __launch_bounds__(256) void reduce_kernel(float* __restrict__ out) {
    const size_t i = (size_t)blockIdx.x * 256 + threadIdx.x;
    float s = 0.f;
#pragma unroll
    for (int c = 0; c < KCH; c++) s += g_opart[(size_t)c * LQ * DIM + i];
    out[i] = s;
}

// ---------------------------------------------------------------------------
extern "C" void kernel_launch(void* const* d_in, const int* in_sizes, int n_in,
                              void* d_out, int out_size) {
    const float* Q = (const float*)d_in[0];
    const float* K = (const float*)d_in[1];
    const float* V = (const float*)d_in[2];
    float* out = (float*)d_out;             // [LQ, DIM]
    float* att = out + (size_t)LQ * DIM;    // [LQ, LK]

    const int smemA = 2 * 128 * STRQ * 2;                       // 69632
    const int smemF = 17408 + 2 * 17408 + 2 * 18432;            // 89088
    cudaFuncSetAttribute(qk_sums_kernel, cudaFuncAttributeMaxDynamicSharedMemorySize, smemA);
    cudaFuncSetAttribute(fused_kernel, cudaFuncAttributeMaxDynamicSharedMemorySize, smemF);

    prep_kernel<<<(LQ * DIM) / 256, 256>>>(Q, K, V);
    qk_sums_kernel<<<dim3(LK / 128, LQ / 128), 256, smemA>>>();
    lred_kernel<<<LQ / 256, 256>>>();
    fused_kernel<<<dim3(KCH, LQ / 64), 256, smemF>>>(att);
    reduce_kernel<<<(LQ * DIM) / 256, 256>>>(out);
}

// round 14
// speedup vs baseline: 1.4807x; 1.4807x over previous
#include <cuda_runtime.h>
#include <cuda_fp16.h>
#include <cstdint>
#include <math.h>

#define LQ 8192
#define LK 8192
#define DIM 128
#define KCH 8
#define SCALE 0.08838834764831845f  // 1/sqrt(128)

#define STRQ 136  // fp16 elems per smem row, 128-wide tiles (272B, conflict-free)
#define STRP 72   // fp16 elems per smem row, V tiles (144B)
#define SSTR 72   // fp32 elems per smem row, S tiles (288B)

// ---------------- device scratch ----------------
__device__ __half g_qh[(size_t)LQ * DIM];
__device__ __half g_kh[(size_t)LK * DIM];
__device__ __half g_vth[(size_t)DIM * LK];          // V^T [d][k]
__device__ float g_lpart[(size_t)LQ * 64];
__device__ float g_il[LQ];
__device__ float g_opart[(size_t)KCH * LQ * DIM];

// ---------------- helpers ----------------
__device__ __forceinline__ uint32_t smem_u32(const void* p) {
    uint32_t a;
    asm("{ .reg .u64 t; cvta.to.shared.u64 t, %1; cvt.u32.u64 %0, t; }" : "=r"(a) : "l"(p));
    return a;
}
__device__ __forceinline__ void ldsm4(uint32_t (&r)[4], uint32_t addr) {
    asm volatile("ldmatrix.sync.aligned.m8n8.x4.shared.b16 {%0,%1,%2,%3}, [%4];"
        : "=r"(r[0]), "=r"(r[1]), "=r"(r[2]), "=r"(r[3]) : "r"(addr));
}
__device__ __forceinline__ void mma16816(float (&c)[4], const uint32_t (&a)[4],
                                         uint32_t b0, uint32_t b1) {
    asm volatile("mma.sync.aligned.m16n8k16.row.col.f32.f16.f16.f32 "
        "{%0,%1,%2,%3}, {%4,%5,%6,%7}, {%8,%9}, {%0,%1,%2,%3};"
        : "+f"(c[0]), "+f"(c[1]), "+f"(c[2]), "+f"(c[3])
        : "r"(a[0]), "r"(a[1]), "r"(a[2]), "r"(a[3]), "r"(b0), "r"(b1));
}
__device__ __forceinline__ void cpasync16(uint32_t dst, const void* src) {
    asm volatile("cp.async.cg.shared.global [%0], [%1], 16;" :: "r"(dst), "l"(src));
}
#define CP_COMMIT() asm volatile("cp.async.commit_group;" ::: "memory")
#define CP_WAIT(N)  asm volatile("cp.async.wait_group %0;" :: "n"(N) : "memory")
__device__ __forceinline__ uint32_t h2u(__half2 h) { return *reinterpret_cast<uint32_t*>(&h); }

// ---------------------------------------------------------------------------
// prep: fp32 -> fp16 (Q prescaled, K, V transposed)
// ---------------------------------------------------------------------------
__global__ __launch_bounds__(256) void prep_kernel(const float* __restrict__ Q,
                                                   const float* __restrict__ K,
                                                   const float* __restrict__ V) {
    size_t i = (size_t)blockIdx.x * 256 + threadIdx.x;
    g_qh[i] = __float2half_rn(Q[i] * SCALE);
    g_kh[i] = __float2half_rn(K[i]);
    size_t kr = i >> 7, d = i & 127;
    g_vth[d * LK + kr] = __float2half_rn(V[i]);
}

// ---------------------------------------------------------------------------
// Kernel A: e = exp(Qs @ K^T) stored to att + per-row partial sums.
// 128m x 128n per CTA, warp tile 32m x 64n (0.375 ldsm/MMA).
// ---------------------------------------------------------------------------
__global__ __launch_bounds__(256, 2) void qk_hmma_kernel(float* __restrict__ att) {
    extern __shared__ __align__(16) char smem[];
    __half* Qh = (__half*)smem;            // [128][STRQ]
    __half* Kh = Qh + 128 * STRQ;          // [128][STRQ]

    const int tid = threadIdx.x, lane = tid & 31, wid = tid >> 5;
    const int m0 = blockIdx.y * 128, n0 = blockIdx.x * 128;

    const uint32_t qhb = smem_u32(Qh), khb = smem_u32(Kh);

#pragma unroll
    for (int i = 0; i < 8; i++) {
        int idx = i * 256 + tid;
        int row = idx >> 4, seg = idx & 15;
        cpasync16(qhb + row * 272 + seg * 16, g_qh + (size_t)(m0 + row) * DIM + seg * 8);
    }
#pragma unroll
    for (int i = 0; i < 8; i++) {
        int idx = i * 256 + tid;
        int row = idx >> 4, seg = idx & 15;
        cpasync16(khb + row * 272 + seg * 16, g_kh + (size_t)(n0 + row) * DIM + seg * 8);
    }
    CP_COMMIT();
    CP_WAIT(0);
    __syncthreads();

    const int wm = (wid >> 1) * 32, wn = (wid & 1) * 64;
    float c[2][8][4];
#pragma unroll
    for (int mi = 0; mi < 2; mi++)
#pragma unroll
        for (int nj = 0; nj < 8; nj++)
#pragma unroll
            for (int e = 0; e < 4; e++) c[mi][nj][e] = 0.f;

    const int arow = lane & 15;
    const int acol = (lane >> 4) * 8;

#pragma unroll
    for (int k16 = 0; k16 < 8; k16++) {
        const int kc = k16 * 16 + acol;
        uint32_t a[2][4], b[4][4];
#pragma unroll
        for (int mi = 0; mi < 2; mi++)
            ldsm4(a[mi], qhb + ((wm + mi * 16 + arow) * STRQ + kc) * 2);
#pragma unroll
        for (int nj = 0; nj < 4; nj++)
            ldsm4(b[nj], khb + ((wn + nj * 16 + arow) * STRQ + kc) * 2);
#pragma unroll
        for (int mi = 0; mi < 2; mi++)
#pragma unroll
            for (int nj = 0; nj < 4; nj++) {
                mma16816(c[mi][2 * nj], a[mi], b[nj][0], b[nj][2]);
                mma16816(c[mi][2 * nj + 1], a[mi], b[nj][1], b[nj][3]);
            }
    }

    // exp in place
#pragma unroll
    for (int mi = 0; mi < 2; mi++)
#pragma unroll
        for (int nj = 0; nj < 8; nj++)
#pragma unroll
            for (int e = 0; e < 4; e++) c[mi][nj][e] = __expf(c[mi][nj][e]);

    // store unnormalized e
    const int r0 = lane >> 2, c0 = (lane & 3) * 2;
#pragma unroll
    for (int mi = 0; mi < 2; mi++) {
#pragma unroll
        for (int nj = 0; nj < 8; nj++) {
            size_t row = (size_t)(m0 + wm + mi * 16 + r0);
            size_t col = (size_t)(n0 + wn + nj * 8 + c0);
            *(float2*)(att + row * LK + col) = make_float2(c[mi][nj][0], c[mi][nj][1]);
            *(float2*)(att + (row + 8) * LK + col) = make_float2(c[mi][nj][2], c[mi][nj][3]);
        }
    }

    // deterministic per-row partial sums over this 128-col block
    __syncthreads();
    float* rs = (float*)smem;  // [128][2]
#pragma unroll
    for (int mi = 0; mi < 2; mi++) {
        float v0 = 0.f, v1 = 0.f;
#pragma unroll
        for (int nj = 0; nj < 8; nj++) {
            v0 += c[mi][nj][0] + c[mi][nj][1];
            v1 += c[mi][nj][2] + c[mi][nj][3];
        }
        v0 += __shfl_xor_sync(0xffffffffu, v0, 1);
        v0 += __shfl_xor_sync(0xffffffffu, v0, 2);
        v1 += __shfl_xor_sync(0xffffffffu, v1, 1);
        v1 += __shfl_xor_sync(0xffffffffu, v1, 2);
        if ((lane & 3) == 0) {
            int r = wm + mi * 16 + (lane >> 2);
            rs[r * 2 + (wid & 1)] = v0;
            rs[(r + 8) * 2 + (wid & 1)] = v1;
        }
    }
    __syncthreads();
    if (tid < 128) {
        g_lpart[(size_t)(m0 + tid) * 64 + blockIdx.x] = rs[tid * 2] + rs[tid * 2 + 1];
    }
}

// ---------------------------------------------------------------------------
// Kernel B: l = sum of partials (fixed order), store 1/l.
// ---------------------------------------------------------------------------
__global__ __launch_bounds__(256) void lred_kernel() {
    const int row = blockIdx.x * 256 + threadIdx.x;
    const float4* p = (const float4*)(g_lpart + (size_t)row * 64);
    float s = 0.f;
#pragma unroll
    for (int i = 0; i < 16; i++) {
        float4 v = p[i];
        s += v.x + v.y + v.z + v.w;
    }
    g_il[row] = 1.0f / s;
}

// ---------------------------------------------------------------------------
// Kernel C (R9 champion, unchanged): att = e*il in place + partial
// Ounnorm = e @ V. S/V stream through 3-deep cp.async rings.
// CTA = 512 threads, 128q x 128d; 16 warps in 8q x 2d grid.
// ---------------------------------------------------------------------------
__global__ __launch_bounds__(512, 1) void pv_hmma_kernel(float* __restrict__ att) {
    extern __shared__ __align__(16) char smem[];
    float* Ss = (float*)smem;                          // [3][128][SSTR] fp32
    __half* Vs = (__half*)(Ss + 3 * 128 * SSTR);       // [3][128][STRP] fp16
    float* ilrow = (float*)(Vs + 3 * 128 * STRP);      // [128]

    const int tid = threadIdx.x, lane = tid & 31, wid = tid >> 5;
    const int q0 = blockIdx.y * 128;
    const int kcnk = blockIdx.x;
    const int kbase = kcnk * (LK / KCH);

    const int qg = (wid & 7) * 16;
    const int dh = (wid >> 3) * 64;
    const int r0 = lane >> 2, c0 = (lane & 3) * 2;
    const int arow = lane & 15, acol = (lane >> 4) * 8;

    if (tid < 128) ilrow[tid] = g_il[q0 + tid];

    const uint32_t sb = smem_u32(Ss), vbb = smem_u32(Vs);
    const int SBUF = 128 * SSTR * 4;
    const int VBUF = 128 * STRP * 2;

#pragma unroll
    for (int st = 0; st < 2; st++) {
        const int kb = kbase + st * 64;
#pragma unroll
        for (int i = 0; i < 4; i++) {
            int idx = i * 512 + tid;
            int row = idx >> 4, seg = idx & 15;
            cpasync16(sb + st * SBUF + row * (SSTR * 4) + seg * 16,
                      att + (size_t)(q0 + row) * LK + kb + seg * 4);
        }
#pragma unroll
        for (int i = 0; i < 2; i++) {
            int idx = i * 512 + tid;
            int row = idx >> 3, seg = idx & 7;
            cpasync16(vbb + st * VBUF + row * (STRP * 2) + seg * 16,
                      g_vth + (size_t)row * LK + kb + seg * 8);
        }
        CP_COMMIT();
    }

    float o[8][4];
#pragma unroll
    for (int nj = 0; nj < 8; nj++)
#pragma unroll
        for (int e = 0; e < 4; e++) o[nj][e] = 0.f;

    for (int t = 0; t < 16; t++) {
        CP_WAIT(1);
        __syncthreads();

        if (t < 14) {
            const int slot = (t + 2) % 3;
            const int kbn = kbase + (t + 2) * 64;
#pragma unroll
            for (int i = 0; i < 4; i++) {
                int idx = i * 512 + tid;
                int row = idx >> 4, seg = idx & 15;
                cpasync16(sb + slot * SBUF + row * (SSTR * 4) + seg * 16,
                          att + (size_t)(q0 + row) * LK + kbn + seg * 4);
            }
#pragma unroll
            for (int i = 0; i < 2; i++) {
                int idx = i * 512 + tid;
                int row = idx >> 3, seg = idx & 7;
                cpasync16(vbb + slot * VBUF + row * (STRP * 2) + seg * 16,
                          g_vth + (size_t)row * LK + kbn + seg * 8);
            }
        }
        CP_COMMIT();

        const int kb = kbase + t * 64;
        const float* Sc = Ss + (t % 3) * 128 * SSTR;
        const uint32_t vcur = vbb + (t % 3) * VBUF;

        // a) normalized att write-back: disjoint tid-partition, float4 stores
#pragma unroll
        for (int i = 0; i < 4; i++) {
            int idx = i * 512 + tid;
            int row = idx >> 4, col4 = (idx & 15) * 4;
            float4 s = *(const float4*)(Sc + row * SSTR + col4);
            const float il = ilrow[row];
            s.x *= il; s.y *= il; s.z *= il; s.w *= il;
            *(float4*)(att + (size_t)(q0 + row) * LK + kb + col4) = s;
        }

        // b) MMA: A-frags = raw e from S smem (cvt only), B from V smem
#pragma unroll
        for (int k16 = 0; k16 < 4; k16++) {
            const int kc = k16 * 16 + c0;
            const float* rp0 = Sc + (qg + r0) * SSTR + kc;
            const float* rp1 = Sc + (qg + r0 + 8) * SSTR + kc;
            float2 s00 = *(const float2*)rp0;
            float2 s10 = *(const float2*)rp1;
            float2 s01 = *(const float2*)(rp0 + 8);
            float2 s11 = *(const float2*)(rp1 + 8);
            uint32_t ah[4];
            ah[0] = h2u(__floats2half2_rn(s00.x, s00.y));
            ah[1] = h2u(__floats2half2_rn(s10.x, s10.y));
            ah[2] = h2u(__floats2half2_rn(s01.x, s01.y));
            ah[3] = h2u(__floats2half2_rn(s11.x, s11.y));

#pragma unroll
            for (int nj = 0; nj < 4; nj++) {
                uint32_t bv[4];
                ldsm4(bv, vcur + ((dh + nj * 16 + arow) * STRP + k16 * 16 + acol) * 2);
                mma16816(o[2 * nj], ah, bv[0], bv[2]);
                mma16816(o[2 * nj + 1], ah, bv[1], bv[3]);
            }
        }
    }

    float* op = g_opart + (size_t)kcnk * ((size_t)LQ * DIM);
#pragma unroll
    for (int n8 = 0; n8 < 8; n8++) {
        size_t row = (size_t)(q0 + qg + r0);
        size_t col = (size_t)(dh + n8 * 8 + c0);
        *(float2*)(op + row * DIM + col) = make_float2(o[n8][0], o[n8][1]);
        *(float2*)(op + (row + 8) * DIM + col) = make_float2(o[n8][2], o[n8][3]);
    }
}

// ---------------------------------------------------------------------------
// Kernel D: reduce KCH partials into out, applying il[row] once.
// ---------------------------------------------------------------------------
__global__ __launch_bounds__(256) void reduce_kernel(float* __restrict__ out) {
    const size_t i = (size_t)blockIdx.x * 256 + threadIdx.x;
    float s = 0.f;
#pragma unroll
    for (int c = 0; c < KCH; c++) s += g_opart[(size_t)c * LQ * DIM + i];
    out[i] = s * g_il[i >> 7];
}

// ---------------------------------------------------------------------------
extern "C" void kernel_launch(void* const* d_in, const int* in_sizes, int n_in,
                              void* d_out, int out_size) {
    const float* Q = (const float*)d_in[0];
    const float* K = (const float*)d_in[1];
    const float* V = (const float*)d_in[2];
    float* out = (float*)d_out;             // [LQ, DIM]
    float* att = out + (size_t)LQ * DIM;    // [LQ, LK]

    const int smemA = 2 * 128 * STRQ * 2;                            // 69632
    const int smemC = 3 * 128 * SSTR * 4 + 3 * 128 * STRP * 2 + 512; // 166400
    cudaFuncSetAttribute(qk_hmma_kernel, cudaFuncAttributeMaxDynamicSharedMemorySize, smemA);
    cudaFuncSetAttribute(pv_hmma_kernel, cudaFuncAttributeMaxDynamicSharedMemorySize, smemC);

    prep_kernel<<<(LQ * DIM) / 256, 256>>>(Q, K, V);
    qk_hmma_kernel<<<dim3(LK / 128, LQ / 128), 256, smemA>>>(att);
    lred_kernel<<<LQ / 256, 256>>>();
    pv_hmma_kernel<<<dim3(KCH, LQ / 128), 512, smemC>>>(att);
    reduce_kernel<<<(LQ * DIM) / 256, 256>>>(out);
}